// round 1
// baseline (speedup 1.0000x reference)
#include <cuda_runtime.h>

// SpectralConv1d: out[b,s,o,k,:] = sum_i complex( x[b,s,i,k,:] * w[o,i,k,:] )
// ROWS = 8*2048 = 16384, D_IN = D_OUT = 32, K = 64, complex as 2 fp32.
//
// Strategy: CUDA-core kernel built around sm_103a packed fma.rn.f32x2.
//  - weights in smem as (wr, wi, -wi, wr) float4, layout [k][i][o]
//  - x in smem splatted as (xr, xr, xi, xi) float4, layout [row][i][kslot] (padded+swizzled)
//  - complex MAC = 2 packed FMAs:
//      (aR,aI) += (xr,xr)*(wr,wi);  (aR,aI) += (xi,xi)*(-wi,wr)
//  - warp owns one k; lane computes 2 rows x 4 o
//  - outputs staged through smem for coalesced float4 stores

#define THREADS        512
#define KT             8          // k's per CTA
#define RTILE          16         // rows per tile
#define TILES_PER_CTA  8          // 128 rows per CTA
#define ROW_GROUPS     128        // 128 * 128 = 16384 rows
#define SX_ROW_STRIDE  257        // float4 units (pad +1 for bank spread)
#define SW_F4          8192       // 8k * 32i * 32o float4
#define SX_F4          (RTILE * SX_ROW_STRIDE)
#define SMEM_BYTES     ((SW_F4 + SX_F4) * 16)
#define STG_ROW_STRIDE 258        // float2 units for output staging

__device__ __forceinline__ void ffma2(unsigned long long &d,
                                      unsigned long long a,
                                      unsigned long long b) {
    asm("fma.rn.f32x2 %0, %1, %2, %0;" : "+l"(d) : "l"(a), "l"(b));
}

__global__ void __launch_bounds__(THREADS, 1)
spectral_f32x2_kernel(const float* __restrict__ X,
                      const float* __restrict__ W,
                      float* __restrict__ O)
{
    extern __shared__ float4 smem[];
    float4* sW = smem;                 // [kl][i][o] : (wr, wi, -wi, wr)
    float4* sX = smem + SW_F4;         // [row][i][kslot] : (xr, xr, xi, xi)
    float2* sStage = reinterpret_cast<float2*>(sX);  // reused after compute

    const int tid  = threadIdx.x;
    const int lane = tid & 31;
    const int warp = tid >> 5;
    const int kl   = warp & 7;         // this warp's local k
    const int rh   = warp >> 3;        // row half (0/1)
    const int og   = lane & 7;         // o group
    const int rp   = lane >> 3;        // row pair within half
    const int row0 = rh * 8 + rp * 2;  // lane's first local row

    const int  kg      = blockIdx.y * KT;                       // global k base
    const long rowBase = (long)blockIdx.x * (RTILE * TILES_PER_CTA);

    // ---- weights -> smem as (wr, wi, -wi, wr), layout [kl][i][o] ----
    for (int idx = tid; idx < SW_F4; idx += THREADS) {
        int klw = idx & 7;
        int iw  = (idx >> 3) & 31;
        int ow  = idx >> 8;
        const float2 wv = *reinterpret_cast<const float2*>(
            W + (size_t)ow * 4096 + (size_t)iw * 128 + (size_t)(kg + klw) * 2);
        sW[klw * 1024 + iw * 32 + ow] = make_float4(wv.x, wv.y, -wv.y, wv.x);
    }

    float4 pf[4];

    // prefetch tile 0 (x gmem is contiguous per (row,i) over this CTA's 8 k's)
    {
        const long tb = rowBase;
        #pragma unroll
        for (int j = 0; j < 4; j++) {
            int idx = tid + j * THREADS;
            int rr = idx >> 7, rem = idx & 127, ii = rem >> 2, k2 = rem & 3;
            pf[j] = *reinterpret_cast<const float4*>(
                X + (tb + rr) * 4096 + ii * 128 + (size_t)(kg + k2 * 2) * 2);
        }
    }
    __syncthreads();  // weights ready

    // store tile 0 (splat + XOR slot swizzle -> bank-floor STS.128)
    #pragma unroll
    for (int j = 0; j < 4; j++) {
        int idx = tid + j * THREADS;
        int rr = idx >> 7, rem = idx & 127, ii = rem >> 2, k2 = rem & 3;
        int s0 = (k2 * 2)     ^ (ii & 7);
        int s1 = (k2 * 2 + 1) ^ (ii & 7);
        float4 v = pf[j];
        sX[rr * SX_ROW_STRIDE + ii * 8 + s0] = make_float4(v.x, v.x, v.y, v.y);
        sX[rr * SX_ROW_STRIDE + ii * 8 + s1] = make_float4(v.z, v.z, v.w, v.w);
    }
    __syncthreads();

    for (int t = 0; t < TILES_PER_CTA; ++t) {
        // prefetch next tile's x into registers (hides LDG under compute)
        if (t + 1 < TILES_PER_CTA) {
            const long tb = rowBase + (long)(t + 1) * RTILE;
            #pragma unroll
            for (int j = 0; j < 4; j++) {
                int idx = tid + j * THREADS;
                int rr = idx >> 7, rem = idx & 127, ii = rem >> 2, k2 = rem & 3;
                pf[j] = *reinterpret_cast<const float4*>(
                    X + (tb + rr) * 4096 + ii * 128 + (size_t)(kg + k2 * 2) * 2);
            }
        }

        // ---- main compute: 2 rows x 4 o per lane, fixed k ----
        unsigned long long acc[2][4];
        #pragma unroll
        for (int r = 0; r < 2; r++)
            #pragma unroll
            for (int o = 0; o < 4; o++) acc[r][o] = 0ULL;

        const ulonglong2* sXu = reinterpret_cast<const ulonglong2*>(sX);
        const ulonglong2* sWu = reinterpret_cast<const ulonglong2*>(sW);
        const int xbase0 = row0 * SX_ROW_STRIDE;
        const int xbase1 = (row0 + 1) * SX_ROW_STRIDE;
        const int wbase  = kl * 1024 + og;

        #pragma unroll 8
        for (int i = 0; i < 32; i++) {
            const int slot = kl ^ (i & 7);
            ulonglong2 xv0 = sXu[xbase0 + i * 8 + slot];  // (xr,xr)|(xi,xi)
            ulonglong2 xv1 = sXu[xbase1 + i * 8 + slot];
            #pragma unroll
            for (int oi = 0; oi < 4; oi++) {
                ulonglong2 wv = sWu[wbase + i * 32 + oi * 8];  // (wr,wi)|(-wi,wr)
                ffma2(acc[0][oi], xv0.x, wv.x);
                ffma2(acc[0][oi], xv0.y, wv.y);
                ffma2(acc[1][oi], xv1.x, wv.x);
                ffma2(acc[1][oi], xv1.y, wv.y);
            }
        }
        __syncthreads();  // everyone done reading sX; safe to reuse as staging

        // ---- stage outputs in smem [row][k][o] for coalesced stores ----
        #pragma unroll
        for (int r = 0; r < 2; r++)
            #pragma unroll
            for (int oi = 0; oi < 4; oi++) {
                int o = og + oi * 8;
                sStage[(row0 + r) * STG_ROW_STRIDE + kl * 32 + o] =
                    *reinterpret_cast<float2*>(&acc[r][oi]);
            }
        __syncthreads();

        // ---- cooperative coalesced store: float4 = (re,im) for k, k+1 ----
        {
            const long tb = rowBase + (long)t * RTILE;
            #pragma unroll
            for (int j = 0; j < 4; j++) {
                int idx = tid + j * THREADS;
                int rr = idx >> 7, rem = idx & 127, oo = rem >> 2, k2 = rem & 3;
                float2 a = sStage[rr * STG_ROW_STRIDE + (k2 * 2)     * 32 + oo];
                float2 b = sStage[rr * STG_ROW_STRIDE + (k2 * 2 + 1) * 32 + oo];
                *reinterpret_cast<float4*>(
                    O + (tb + rr) * 4096 + oo * 128 + (size_t)(kg + k2 * 2) * 2)
                    = make_float4(a.x, a.y, b.x, b.y);
            }
        }
        __syncthreads();

        // ---- commit prefetched x tile to smem ----
        if (t + 1 < TILES_PER_CTA) {
            #pragma unroll
            for (int j = 0; j < 4; j++) {
                int idx = tid + j * THREADS;
                int rr = idx >> 7, rem = idx & 127, ii = rem >> 2, k2 = rem & 3;
                int s0 = (k2 * 2)     ^ (ii & 7);
                int s1 = (k2 * 2 + 1) ^ (ii & 7);
                float4 v = pf[j];
                sX[rr * SX_ROW_STRIDE + ii * 8 + s0] = make_float4(v.x, v.x, v.y, v.y);
                sX[rr * SX_ROW_STRIDE + ii * 8 + s1] = make_float4(v.z, v.z, v.w, v.w);
            }
            __syncthreads();
        }
    }
}

extern "C" void kernel_launch(void* const* d_in, const int* in_sizes, int n_in,
                              void* d_out, int out_size)
{
    const float* x = (const float*)d_in[0];   // (8,2048,32,64,2) fp32
    const float* w = (const float*)d_in[1];   // (32,32,64,2) fp32
    float* out = (float*)d_out;               // (8,2048,32,64,2) fp32

    cudaFuncSetAttribute(spectral_f32x2_kernel,
                         cudaFuncAttributeMaxDynamicSharedMemorySize, SMEM_BYTES);
    dim3 grid(ROW_GROUPS, 64 / KT);           // 128 row groups x 8 k-splits
    spectral_f32x2_kernel<<<grid, THREADS, SMEM_BYTES>>>(x, w, out);
}

// round 2
// speedup vs baseline: 1.1177x; 1.1177x over previous
#include <cuda_runtime.h>

// SpectralConv1d: out[row,o,k,:] = sum_i complex( x[row,i,k,:] * w[o,i,k,:] )
// rows = 8*2048 = 16384, i = o = 32, k = 64, complex = 2 fp32.
//
// f32x2 kernel, round 2: fma-bound blocking.
//  - warp <-> one k; lane tile = 4 rows x 8 o  (64 FFMA2 per i, 12 LDS per i)
//  - smem: sW [k][i][o] float4 (wr,wi,wi,wr)  = 128KB
//          sX [row][k][i]  float2 (xr,xi), row pad +1 f2 = 64.25KB (reused as out stage)
//  - complex MAC: acc(accR,accI) += (xr,xr)*(wr,wi) + (-xi,xi)*(wi,wr)
//  - x for next tile register-prefetched in 2 batches; outputs staged in smem
//    and stored as sector-perfect float4.

#define THREADS 256
#define KT      8           // k per CTA
#define RT      32          // rows per tile
#define TILES   4           // tiles per CTA -> 128 rows/CTA
#define RS      257         // sX row stride in float2 (pad +1)
#define SW_F4   8192        // 8k * 32i * 32o
#define SX_F2   (RT * RS)   // 8224
#define SMEM_BYTES (SW_F4 * 16 + SX_F2 * 8)   // 131072 + 65792 = 196864

__device__ __forceinline__ void ffma2(unsigned long long &d,
                                      unsigned long long a,
                                      unsigned long long b) {
    asm("fma.rn.f32x2 %0, %1, %2, %0;" : "+l"(d) : "l"(a), "l"(b));
}
__device__ __forceinline__ unsigned long long pack2(float lo, float hi) {
    unsigned long long r;
    asm("mov.b64 %0, {%1, %2};" : "=l"(r) : "f"(lo), "f"(hi));
    return r;
}

__global__ void __launch_bounds__(THREADS, 1)
spectral_r2_kernel(const float* __restrict__ X,
                   const float* __restrict__ W,
                   float* __restrict__ O)
{
    extern __shared__ float smemf[];
    float4* sW4 = reinterpret_cast<float4*>(smemf);              // [kl][i][o]
    float2* sX  = reinterpret_cast<float2*>(smemf + SW_F4 * 4);  // [row][k][i] (+stage reuse)
    const ulonglong2* sWu = reinterpret_cast<const ulonglong2*>(sW4);

    const int tid  = threadIdx.x;
    const int lane = tid & 31;
    const int warp = tid >> 5;          // == kl (local k)
    const int og   = lane & 3;          // o group (o = oi*4 + og)
    const int rp   = lane >> 2;         // row group (rows rp*4 .. rp*4+3)
    const int kg   = blockIdx.x * KT;   // global k base
    const long rowBase = (long)blockIdx.y * (RT * TILES);

    // ---- weights -> smem as (wr, wi, wi, wr), layout [k][i][o] ----
    #pragma unroll 4
    for (int it = 0; it < 32; ++it) {
        int idx = tid + it * THREADS;
        int o = idx & 31, i = (idx >> 5) & 31, kw = idx >> 10;
        float2 wv = *reinterpret_cast<const float2*>(
            W + (size_t)o * 4096 + i * 128 + (size_t)(kg + kw) * 2);
        sW4[kw * 1024 + i * 32 + o] = make_float4(wv.x, wv.y, wv.y, wv.x);
    }

    // ---- tile 0 x fill: [row][k][i] float2 ----
    {
        #pragma unroll 4
        for (int it = 0; it < 16; ++it) {
            int idx = tid + it * THREADS;
            int i = idx & 31, k2 = (idx >> 5) & 3, row = idx >> 7;
            float4 v = *reinterpret_cast<const float4*>(
                X + (rowBase + row) * 4096 + i * 128 + (size_t)(kg + k2 * 2) * 2);
            sX[row * RS + (2 * k2)     * 32 + i] = make_float2(v.x, v.y);
            sX[row * RS + (2 * k2 + 1) * 32 + i] = make_float2(v.z, v.w);
        }
    }
    __syncthreads();

    float4 pfA[8], pfB[8];

    for (int t = 0; t < TILES; ++t) {
        const long tb = rowBase + (long)t * RT;

        // prefetch batch A of next tile (rows 0..15)
        if (t + 1 < TILES) {
            const long nb = tb + RT;
            #pragma unroll
            for (int j = 0; j < 8; ++j) {
                int idx = tid + j * THREADS;
                int i = idx & 31, k2 = (idx >> 5) & 3, row = idx >> 7;
                pfA[j] = *reinterpret_cast<const float4*>(
                    X + (nb + row) * 4096 + i * 128 + (size_t)(kg + k2 * 2) * 2);
            }
        }

        // ---- compute: 4 rows x 8 o per lane, fixed k ----
        unsigned long long acc[4][8];
        #pragma unroll
        for (int r = 0; r < 4; ++r)
            #pragma unroll
            for (int oi = 0; oi < 8; ++oi) acc[r][oi] = 0ULL;

        const int xb = warp * 32;            // + row*RS + i
        const int wb = warp * 1024 + og;     // + i*32 + oi*4

        #pragma unroll 4
        for (int i = 0; i < 32; ++i) {
            unsigned long long xs1[4], xs2[4];
            #pragma unroll
            for (int r = 0; r < 4; ++r) {
                float2 xv = sX[(rp * 4 + r) * RS + xb + i];
                xs1[r] = pack2(xv.x, xv.x);
                xs2[r] = pack2(-xv.y, xv.y);
            }
            #pragma unroll
            for (int oi = 0; oi < 8; ++oi) {
                ulonglong2 wv = sWu[wb + i * 32 + oi * 4];  // (wr,wi)|(wi,wr)
                #pragma unroll
                for (int r = 0; r < 4; ++r) {
                    ffma2(acc[r][oi], xs1[r], wv.x);
                    ffma2(acc[r][oi], xs2[r], wv.y);
                }
            }
        }

        // prefetch batch B of next tile (rows 16..31)
        if (t + 1 < TILES) {
            const long nb = tb + RT;
            #pragma unroll
            for (int j = 0; j < 8; ++j) {
                int idx = tid + (j + 8) * THREADS;
                int i = idx & 31, k2 = (idx >> 5) & 3, row = idx >> 7;
                pfB[j] = *reinterpret_cast<const float4*>(
                    X + (nb + row) * 4096 + i * 128 + (size_t)(kg + k2 * 2) * 2);
            }
        }
        __syncthreads();   // sX reads done -> safe to overwrite as stage

        // ---- stage outputs: sX reused as [row][o][k] float2 (row stride RS) ----
        #pragma unroll
        for (int r = 0; r < 4; ++r)
            #pragma unroll
            for (int oi = 0; oi < 8; ++oi) {
                float2 v = *reinterpret_cast<float2*>(&acc[r][oi]);
                sX[(rp * 4 + r) * RS + (oi * 4 + og) * 8 + warp] = v;
            }
        __syncthreads();

        // ---- coalesced store: float4 = 2 k's per thread ----
        #pragma unroll 4
        for (int it = 0; it < 16; ++it) {
            int idx = tid + it * THREADS;
            int k2 = idx & 3, o = (idx >> 2) & 31, row = idx >> 7;
            float2 a = sX[row * RS + o * 8 + 2 * k2];
            float2 b = sX[row * RS + o * 8 + 2 * k2 + 1];
            *reinterpret_cast<float4*>(
                O + (tb + row) * 4096 + o * 128 + (size_t)(kg + k2 * 2) * 2)
                = make_float4(a.x, a.y, b.x, b.y);
        }
        __syncthreads();   // stage consumed -> safe to refill sX

        // ---- commit prefetched next-tile x ----
        if (t + 1 < TILES) {
            #pragma unroll
            for (int j = 0; j < 8; ++j) {
                int idx = tid + j * THREADS;
                int i = idx & 31, k2 = (idx >> 5) & 3, row = idx >> 7;
                float4 v = pfA[j];
                sX[row * RS + (2 * k2)     * 32 + i] = make_float2(v.x, v.y);
                sX[row * RS + (2 * k2 + 1) * 32 + i] = make_float2(v.z, v.w);
            }
            #pragma unroll
            for (int j = 0; j < 8; ++j) {
                int idx = tid + (j + 8) * THREADS;
                int i = idx & 31, k2 = (idx >> 5) & 3, row = idx >> 7;
                float4 v = pfB[j];
                sX[row * RS + (2 * k2)     * 32 + i] = make_float2(v.x, v.y);
                sX[row * RS + (2 * k2 + 1) * 32 + i] = make_float2(v.z, v.w);
            }
            __syncthreads();
        }
    }
}

extern "C" void kernel_launch(void* const* d_in, const int* in_sizes, int n_in,
                              void* d_out, int out_size)
{
    const float* x = (const float*)d_in[0];   // (8,2048,32,64,2) fp32
    const float* w = (const float*)d_in[1];   // (32,32,64,2) fp32
    float* out = (float*)d_out;               // (8,2048,32,64,2) fp32

    cudaFuncSetAttribute(spectral_r2_kernel,
                         cudaFuncAttributeMaxDynamicSharedMemorySize, SMEM_BYTES);
    dim3 grid(64 / KT, 16384 / (RT * TILES));  // (8, 128); k fastest for L2 reuse
    spectral_r2_kernel<<<grid, THREADS, SMEM_BYTES>>>(x, w, out);
}